// round 1
// baseline (speedup 1.0000x reference)
#include <cuda_runtime.h>

#define NN 32
#define CC 64
#define TT 400
#define VV 27
#define SS 2
#define ICC 16
#define OO 64
#define LEAKK 0.1f
#define EPSS 1e-5f

#define TCH 16            // t-chunks for kernel A
#define TLEN (TT/TCH)     // 25
#define TB 4              // t per block kernel C
#define TDD 25            // t per block kernel D

// Scratch (static device globals — allocation-free)
__device__ float g_att_part[NN*TCH*SS*VV*VV];   // ~3 MB
__device__ float g_att[NN*SS*VV*VV];
__device__ float g_y2[(size_t)NN*CC*TT*VV];     // ~88.5 MB

// ---------------------------------------------------------------------------
// Kernel A: y = x + pe ; qk = W_in*y + b_in ; partial att accumulation over t
// grid (TCH, NN), 256 threads (8 o-groups x 32 lanes)
// ---------------------------------------------------------------------------
__global__ void __launch_bounds__(256) k_att_part(const float* __restrict__ x,
                                                  const float* __restrict__ pe,
                                                  const float* __restrict__ W_in,
                                                  const float* __restrict__ b_in) {
    __shared__ float sW[64*64];
    __shared__ float sb[64];
    __shared__ float sy[64*28];
    __shared__ float sqk[64*28];

    int n = blockIdx.y, chunk = blockIdx.x;
    int tid = threadIdx.x;
    int og = tid >> 5, vv = tid & 31;

    for (int i = tid; i < 64*64; i += 256) sW[i] = W_in[i];
    if (tid < 64) sb[tid] = b_in[tid];

    // att tiles: 2 s * 14 u2 * 14 v2 = 392 tiles of 2x2 (u,v)
    float accA[4] = {0.f,0.f,0.f,0.f};
    float accB[4] = {0.f,0.f,0.f,0.f};
    int tileA = tid;            // 0..255  (always < 392)
    int tileB = tid + 256;      // 256..511 (valid < 392)

    int sA = tileA / 196; int rA = tileA - sA*196;
    int uA = (rA/14)*2, vA = (rA%14)*2;
    int sB = tileB / 196; int rB = tileB - sB*196;
    int uB = (rB/14)*2, vB = (rB%14)*2;

    __syncthreads();

    for (int tt = 0; tt < TLEN; ++tt) {
        int t = chunk*TLEN + tt;
        for (int i = tid; i < 64*27; i += 256) {
            int c = i / 27, v = i - c*27;
            sy[c*28+v] = x[(((size_t)n*64 + c)*400 + t)*27 + v]
                       + pe[((size_t)c*400 + t)*27 + v];
        }
        __syncthreads();

        // projection: qk[o][vv], 8 outputs per thread
        if (vv < 27) {
            float a8[8];
            #pragma unroll
            for (int i = 0; i < 8; ++i) a8[i] = sb[og*8+i];
            #pragma unroll 4
            for (int c = 0; c < 64; ++c) {
                float yv = sy[c*28+vv];
                #pragma unroll
                for (int i = 0; i < 8; ++i)
                    a8[i] = fmaf(sW[(og*8+i)*64 + c], yv, a8[i]);
            }
            #pragma unroll
            for (int i = 0; i < 8; ++i) sqk[(og*8+i)*28 + vv] = a8[i];
        }
        __syncthreads();

        // accumulate q.k per 2x2 (u,v) tile
        {
            const float* q = sqk + (sA*16)*28;
            const float* k = sqk + (32 + sA*16)*28;
            #pragma unroll 4
            for (int c = 0; c < 16; ++c) {
                float q0 = q[c*28+uA];
                float q1 = (uA < 26) ? q[c*28+uA+1] : 0.f;
                float k0 = k[c*28+vA];
                float k1 = (vA < 26) ? k[c*28+vA+1] : 0.f;
                accA[0] = fmaf(q0,k0,accA[0]);
                accA[1] = fmaf(q0,k1,accA[1]);
                accA[2] = fmaf(q1,k0,accA[2]);
                accA[3] = fmaf(q1,k1,accA[3]);
            }
        }
        if (tileB < 392) {
            const float* q = sqk + (sB*16)*28;
            const float* k = sqk + (32 + sB*16)*28;
            #pragma unroll 4
            for (int c = 0; c < 16; ++c) {
                float q0 = q[c*28+uB];
                float q1 = (uB < 26) ? q[c*28+uB+1] : 0.f;
                float k0 = k[c*28+vB];
                float k1 = (vB < 26) ? k[c*28+vB+1] : 0.f;
                accB[0] = fmaf(q0,k0,accB[0]);
                accB[1] = fmaf(q0,k1,accB[1]);
                accB[2] = fmaf(q1,k0,accB[2]);
                accB[3] = fmaf(q1,k1,accB[3]);
            }
        }
        __syncthreads();
    }

    // write partial sums
    {
        float* base = g_att_part + (((size_t)n*TCH + chunk)*SS + sA)*729;
        base[uA*27+vA] = accA[0];
        if (vA+1 < 27)              base[uA*27+vA+1]     = accA[1];
        if (uA+1 < 27)              base[(uA+1)*27+vA]   = accA[2];
        if (uA+1 < 27 && vA+1 < 27) base[(uA+1)*27+vA+1] = accA[3];
    }
    if (tileB < 392) {
        float* base = g_att_part + (((size_t)n*TCH + chunk)*SS + sB)*729;
        base[uB*27+vB] = accB[0];
        if (vB+1 < 27)              base[uB*27+vB+1]     = accB[1];
        if (uB+1 < 27)              base[(uB+1)*27+vB]   = accB[2];
        if (uB+1 < 27 && vB+1 < 27) base[(uB+1)*27+vB+1] = accB[3];
    }
}

// ---------------------------------------------------------------------------
// Kernel B: reduce chunks + tanh/alpha/att0
// ---------------------------------------------------------------------------
__global__ void __launch_bounds__(256) k_att_final(const float* __restrict__ alphas,
                                                   const float* __restrict__ att0) {
    int idx = blockIdx.x*256 + threadIdx.x;
    if (idx >= NN*SS*729) return;
    int n = idx / (SS*729);
    int r = idx - n*(SS*729);
    int s = r / 729;
    int uv = r - s*729;
    float sum = 0.f;
    #pragma unroll
    for (int ch = 0; ch < TCH; ++ch)
        sum += g_att_part[(((size_t)n*TCH + ch)*SS + s)*729 + uv];
    g_att[idx] = tanhf(sum * (1.0f/(16.f*400.f))) * alphas[s] + att0[s*729 + uv];
}

// ---------------------------------------------------------------------------
// Kernel C: xa = x@att ; h = lrelu(x + bn(W_out xa)) ; y2 = lrelu(x + bn(W_ff h))
// grid (TT/TB, NN), 256 threads, dynamic smem
// ---------------------------------------------------------------------------
__global__ void __launch_bounds__(256) k_main(const float* __restrict__ x,
        const float* __restrict__ W_out, const float* __restrict__ b_out,
        const float* __restrict__ g_out, const float* __restrict__ be_out,
        const float* __restrict__ m_out, const float* __restrict__ v_out,
        const float* __restrict__ W_ff,  const float* __restrict__ b_ff,
        const float* __restrict__ g_ff,  const float* __restrict__ be_ff,
        const float* __restrict__ m_ff,  const float* __restrict__ v_ff) {
    extern __shared__ float sm[];
    float* sWo      = sm;               // 8192
    float* sWf      = sWo + 8192;       // 4096
    float* satt     = sWf + 4096;       // 1458
    float* sx       = satt + 1458;      // 64*28 = 1792
    float* sxa      = sx + 1792;        // 128*28 = 3584
    float* sh       = sxa + 3584;       // 1792
    float* sscale_o = sh + 1792;        // 64
    float* sshift_o = sscale_o + 64;    // 64
    float* sscale_f = sshift_o + 64;    // 64
    float* sshift_f = sscale_f + 64;    // 64

    int n = blockIdx.y, tb = blockIdx.x;
    int tid = threadIdx.x, og = tid >> 5, vv = tid & 31;

    for (int i = tid; i < 8192; i += 256) sWo[i] = W_out[i];
    for (int i = tid; i < 4096; i += 256) sWf[i] = W_ff[i];
    for (int i = tid; i < 1458; i += 256) satt[i] = g_att[(size_t)n*1458 + i];
    if (tid < 64) {
        float sc = g_out[tid]*rsqrtf(v_out[tid]+EPSS);
        sscale_o[tid] = sc;
        sshift_o[tid] = be_out[tid] + sc*(b_out[tid]-m_out[tid]);
        float sf = g_ff[tid]*rsqrtf(v_ff[tid]+EPSS);
        sscale_f[tid] = sf;
        sshift_f[tid] = be_ff[tid] + sf*(b_ff[tid]-m_ff[tid]);
    }
    __syncthreads();

    for (int tt = 0; tt < TB; ++tt) {
        int t = tb*TB + tt;
        for (int i = tid; i < 64*27; i += 256) {
            int c = i / 27, v = i - c*27;
            sx[c*28+v] = x[(((size_t)n*64 + c)*400 + t)*27 + v];
        }
        __syncthreads();

        // xa[s*64+c][vv] = sum_u x[c][u] * att[s][u][vv]; 16 c per thread
        if (vv < 27) {
            int s = og >> 2, c0 = (og & 3) * 16;
            float ratt[27];
            #pragma unroll
            for (int u = 0; u < 27; ++u) ratt[u] = satt[s*729 + u*27 + vv];
            #pragma unroll 2
            for (int ci = 0; ci < 16; ++ci) {
                int c = c0 + ci;
                float a = 0.f;
                #pragma unroll
                for (int u = 0; u < 27; ++u)
                    a = fmaf(sx[c*28+u], ratt[u], a);
                sxa[(s*64+c)*28 + vv] = a;
            }
        }
        __syncthreads();

        // h = lrelu(x + bn(W_out @ xa))
        if (vv < 27) {
            float a8[8] = {0.f,0.f,0.f,0.f,0.f,0.f,0.f,0.f};
            #pragma unroll 4
            for (int j = 0; j < 128; ++j) {
                float xj = sxa[j*28+vv];
                #pragma unroll
                for (int io = 0; io < 8; ++io)
                    a8[io] = fmaf(sWo[(og*8+io)*128 + j], xj, a8[io]);
            }
            #pragma unroll
            for (int io = 0; io < 8; ++io) {
                int o = og*8+io;
                float val = sx[o*28+vv] + a8[io]*sscale_o[o] + sshift_o[o];
                sh[o*28+vv] = fmaxf(val, LEAKK*val);
            }
        }
        __syncthreads();

        // y2 = lrelu(x + bn(W_ff @ h))
        if (vv < 27) {
            float a8[8] = {0.f,0.f,0.f,0.f,0.f,0.f,0.f,0.f};
            #pragma unroll 4
            for (int j = 0; j < 64; ++j) {
                float hj = sh[j*28+vv];
                #pragma unroll
                for (int io = 0; io < 8; ++io)
                    a8[io] = fmaf(sWf[(og*8+io)*64 + j], hj, a8[io]);
            }
            #pragma unroll
            for (int io = 0; io < 8; ++io) {
                int o = og*8+io;
                float val = sx[o*28+vv] + a8[io]*sscale_f[o] + sshift_f[o];
                g_y2[(((size_t)n*64 + o)*400 + t)*27 + vv] = fmaxf(val, LEAKK*val);
            }
        }
        __syncthreads();
    }
}

// ---------------------------------------------------------------------------
// Kernel D: z = lrelu(y2 + bn(conv_t(y2) + b_t)), 3-tap temporal conv, ring buf
// grid (TT/TDD, NN), 256 threads, dynamic smem
// ---------------------------------------------------------------------------
__global__ void __launch_bounds__(256) k_temporal(const float* __restrict__ W_t,
        const float* __restrict__ b_t, const float* __restrict__ g_t,
        const float* __restrict__ be_t, const float* __restrict__ m_t,
        const float* __restrict__ v_t, float* __restrict__ out) {
    extern __shared__ float sm[];
    float* sWt    = sm;                 // 64*64*3 = 12288
    float* ring   = sWt + 12288;        // 3 * 1792
    float* sscale = ring + 3*1792;      // 64
    float* sshift = sscale + 64;        // 64

    int n = blockIdx.y, tb = blockIdx.x;
    int tid = threadIdx.x, og = tid >> 5, vv = tid & 31;

    for (int i = tid; i < 12288; i += 256) sWt[i] = W_t[i];
    if (tid < 64) {
        float sc = g_t[tid]*rsqrtf(v_t[tid]+EPSS);
        sscale[tid] = sc;
        sshift[tid] = be_t[tid] + sc*(b_t[tid]-m_t[tid]);
    }
    int t0 = tb*TDD;

    // slice loader into ring slot (t mod 3)
    auto load_slice = [&](int t) {
        float* dst = ring + ((t+3)%3)*1792;
        for (int i = tid; i < 64*27; i += 256) {
            int c = i / 27, v = i - c*27;
            dst[c*28+v] = (t >= 0 && t < 400)
                        ? g_y2[(((size_t)n*64 + c)*400 + t)*27 + v] : 0.f;
        }
    };
    load_slice(t0-1);
    load_slice(t0);
    __syncthreads();

    for (int tt = 0; tt < TDD; ++tt) {
        int t = t0 + tt;
        load_slice(t+1);
        __syncthreads();
        const float* sm1 = ring + ((t-1+3)%3)*1792;
        const float* s0  = ring + ((t  )%3)*1792;
        const float* sp1 = ring + ((t+1)%3)*1792;
        if (vv < 27) {
            float a8[8] = {0.f,0.f,0.f,0.f,0.f,0.f,0.f,0.f};
            #pragma unroll 2
            for (int i = 0; i < 64; ++i) {
                float ym = sm1[i*28+vv];
                float y0 = s0 [i*28+vv];
                float yp = sp1[i*28+vv];
                #pragma unroll
                for (int io = 0; io < 8; ++io) {
                    const float* w = sWt + ((og*8+io)*64 + i)*3;
                    a8[io] = fmaf(w[0], ym, fmaf(w[1], y0, fmaf(w[2], yp, a8[io])));
                }
            }
            #pragma unroll
            for (int io = 0; io < 8; ++io) {
                int o = og*8+io;
                float z = a8[io]*sscale[o] + sshift[o];
                float val = s0[o*28+vv] + z;
                out[(((size_t)n*64 + o)*400 + t)*27 + vv] = fmaxf(val, LEAKK*val);
            }
        }
        __syncthreads();
    }
}

// ---------------------------------------------------------------------------
extern "C" void kernel_launch(void* const* d_in, const int* in_sizes, int n_in,
                              void* d_out, int out_size) {
    const float* x      = (const float*)d_in[0];
    const float* pe     = (const float*)d_in[1];
    const float* W_in   = (const float*)d_in[2];
    const float* b_in   = (const float*)d_in[3];
    const float* alphas = (const float*)d_in[4];
    const float* att0   = (const float*)d_in[5];
    const float* W_out  = (const float*)d_in[6];
    const float* b_out  = (const float*)d_in[7];
    const float* g_out  = (const float*)d_in[8];
    const float* be_out = (const float*)d_in[9];
    const float* m_out  = (const float*)d_in[10];
    const float* v_out  = (const float*)d_in[11];
    const float* W_ff   = (const float*)d_in[12];
    const float* b_ff   = (const float*)d_in[13];
    const float* g_ff   = (const float*)d_in[14];
    const float* be_ff  = (const float*)d_in[15];
    const float* m_ff   = (const float*)d_in[16];
    const float* v_ff   = (const float*)d_in[17];
    const float* W_t    = (const float*)d_in[18];
    const float* b_t    = (const float*)d_in[19];
    const float* g_t    = (const float*)d_in[20];
    const float* be_t   = (const float*)d_in[21];
    const float* m_t    = (const float*)d_in[22];
    const float* v_t    = (const float*)d_in[23];
    float* out = (float*)d_out;

    const int smemC = (8192+4096+1458+1792+3584+1792+4*64) * sizeof(float);
    const int smemD = (12288+3*1792+2*64) * sizeof(float);
    cudaFuncSetAttribute(k_main, cudaFuncAttributeMaxDynamicSharedMemorySize, smemC);
    cudaFuncSetAttribute(k_temporal, cudaFuncAttributeMaxDynamicSharedMemorySize, smemD);

    k_att_part<<<dim3(TCH, NN), 256>>>(x, pe, W_in, b_in);
    k_att_final<<<(NN*SS*729 + 255)/256, 256>>>(alphas, att0);
    k_main<<<dim3(TT/TB, NN), 256, smemC>>>(x, W_out, b_out, g_out, be_out, m_out, v_out,
                                            W_ff, b_ff, g_ff, be_ff, m_ff, v_ff);
    k_temporal<<<dim3(TT/TDD, NN), 256, smemD>>>(W_t, b_t, g_t, be_t, m_t, v_t, out);
}

// round 6
// speedup vs baseline: 1.0029x; 1.0029x over previous
#include <cuda_runtime.h>

#define NN 32
#define CC 64
#define TT 400
#define VV 27
#define SS 2
#define ICC 16
#define OO 64
#define LEAKK 0.1f
#define EPSS 1e-5f

#define TCH 25            // t-chunks for kernel A (16 t each, 8 pairs)

typedef unsigned long long ull;

__device__ __forceinline__ ull fma2(ull a, ull b, ull c) {
    ull d;
    asm("fma.rn.f32x2 %0, %1, %2, %3;" : "=l"(d) : "l"(a), "l"(b), "l"(c));
    return d;
}
__device__ __forceinline__ ull pk(float lo, float hi) {
    ull r;
    asm("mov.b64 %0, {%1, %2};" : "=l"(r) : "f"(lo), "f"(hi));
    return r;
}
__device__ __forceinline__ void upk(ull v, float& lo, float& hi) {
    asm("mov.b64 {%0, %1}, %2;" : "=f"(lo), "=f"(hi) : "l"(v));
}

// Scratch (static device globals — allocation-free)
__device__ float g_att_part[NN*TCH*SS*VV*VV];
__device__ float g_att[NN*SS*VV*VV];
__device__ float g_y2[(size_t)NN*TT*1792];      // [n][t][c*28+v], padded

// ---------------------------------------------------------------------------
// Kernel A: y = x + pe ; qk = W_in*y + b_in ; partial att accum over 16 t
// grid (25, NN), 256 threads. Packed over t-pairs.
// ---------------------------------------------------------------------------
__global__ void __launch_bounds__(256,1) k_att_part(const float* __restrict__ x,
                                                    const float* __restrict__ pe,
                                                    const float* __restrict__ W_in,
                                                    const float* __restrict__ b_in) {
    extern __shared__ ull smU[];
    ull* sW2  = smU;            // 4096  (dup W_in, [c][o])
    ull* sy2  = sW2 + 4096;     // 1792  ([c][v] t-pair)
    ull* sqk2 = sy2 + 1792;     // 1792  ([o][v] t-pair)
    float* sb = (float*)(sqk2 + 1792);  // 64

    int n = blockIdx.y, chunk = blockIdx.x;
    int tid = threadIdx.x, og = tid >> 5, vv = tid & 31;

    for (int i = tid; i < 4096; i += 256) {
        int o = i & 63, c = i >> 6;
        float w = W_in[o*64 + c];
        sW2[i] = pk(w, w);
    }
    if (tid < 64) sb[tid] = b_in[tid];

    // att tiles: 2 s * 14 u2 * 14 v2 = 392 tiles of 2x2 (u,v)
    ull accA[4] = {0,0,0,0};
    ull accB[4] = {0,0,0,0};
    int tileA = tid, tileB = tid + 256;
    int sA = tileA / 196; int rA = tileA - sA*196;
    int uA = (rA/14)*2, vA = (rA%14)*2;
    int sB = tileB / 196; int rB = tileB - sB*196;
    int uB = (rB/14)*2, vB = (rB%14)*2;

    __syncthreads();

    for (int it = 0; it < 8; ++it) {
        int t0 = chunk*16 + it*2;
        for (int i = tid; i < 3456; i += 256) {
            int c = i / 54, r = i - c*54, tt = r / 27, v = r - tt*27;
            float val = x[(((size_t)n*64 + c)*400 + t0 + tt)*27 + v]
                      + pe[((size_t)c*400 + t0 + tt)*27 + v];
            ((float*)sy2)[2*(c*28 + v) + tt] = val;
        }
        __syncthreads();

        // projection: qk[o][vv] packed pair; 8 outputs per thread
        if (vv < 27) {
            ull acc[8];
            #pragma unroll
            for (int io = 0; io < 8; ++io) { float b = sb[og*8+io]; acc[io] = pk(b, b); }
            #pragma unroll 2
            for (int c = 0; c < 64; ++c) {
                ull yp = sy2[c*28 + vv];
                const ull* wrow = sW2 + c*64 + og*8;
                #pragma unroll
                for (int io = 0; io < 8; ++io)
                    acc[io] = fma2(wrow[io], yp, acc[io]);
            }
            #pragma unroll
            for (int io = 0; io < 8; ++io) sqk2[(og*8+io)*28 + vv] = acc[io];
        } else if (vv == 27) {
            // zero pad column so u+1 / v+1 loads are safe
            #pragma unroll
            for (int io = 0; io < 8; ++io) sqk2[(og*8+io)*28 + 27] = 0ULL;
        }
        __syncthreads();

        // q.k per 2x2 (u,v) tile, both t of the pair live in the two halves
        {
            const ull* q  = sqk2 + (sA*16)*28;
            const ull* kk = sqk2 + (32 + sA*16)*28;
            #pragma unroll 4
            for (int c = 0; c < 16; ++c) {
                ull q0 = q[c*28+uA],  q1 = q[c*28+uA+1];
                ull k0 = kk[c*28+vA], k1 = kk[c*28+vA+1];
                accA[0] = fma2(q0,k0,accA[0]); accA[1] = fma2(q0,k1,accA[1]);
                accA[2] = fma2(q1,k0,accA[2]); accA[3] = fma2(q1,k1,accA[3]);
            }
        }
        if (tileB < 392) {
            const ull* q  = sqk2 + (sB*16)*28;
            const ull* kk = sqk2 + (32 + sB*16)*28;
            #pragma unroll 4
            for (int c = 0; c < 16; ++c) {
                ull q0 = q[c*28+uB],  q1 = q[c*28+uB+1];
                ull k0 = kk[c*28+vB], k1 = kk[c*28+vB+1];
                accB[0] = fma2(q0,k0,accB[0]); accB[1] = fma2(q0,k1,accB[1]);
                accB[2] = fma2(q1,k0,accB[2]); accB[3] = fma2(q1,k1,accB[3]);
            }
        }
        __syncthreads();
    }

    // horizontal-reduce pairs and store partials
    {
        float* base = g_att_part + (((size_t)n*TCH + chunk)*SS + sA)*729;
        float a0,b0; upk(accA[0],a0,b0); base[uA*27+vA] = a0+b0;
        float a1,b1; upk(accA[1],a1,b1);
        float a2,b2; upk(accA[2],a2,b2);
        float a3,b3; upk(accA[3],a3,b3);
        if (vA+1 < 27)              base[uA*27+vA+1]     = a1+b1;
        if (uA+1 < 27)              base[(uA+1)*27+vA]   = a2+b2;
        if (uA+1 < 27 && vA+1 < 27) base[(uA+1)*27+vA+1] = a3+b3;
    }
    if (tileB < 392) {
        float* base = g_att_part + (((size_t)n*TCH + chunk)*SS + sB)*729;
        float a0,b0; upk(accB[0],a0,b0); base[uB*27+vB] = a0+b0;
        float a1,b1; upk(accB[1],a1,b1);
        float a2,b2; upk(accB[2],a2,b2);
        float a3,b3; upk(accB[3],a3,b3);
        if (vB+1 < 27)              base[uB*27+vB+1]     = a1+b1;
        if (uB+1 < 27)              base[(uB+1)*27+vB]   = a2+b2;
        if (uB+1 < 27 && vB+1 < 27) base[(uB+1)*27+vB+1] = a3+b3;
    }
}

// ---------------------------------------------------------------------------
// Kernel B: reduce chunks + tanh/alpha/att0
// ---------------------------------------------------------------------------
__global__ void __launch_bounds__(256) k_att_final(const float* __restrict__ alphas,
                                                   const float* __restrict__ att0) {
    int idx = blockIdx.x*256 + threadIdx.x;
    if (idx >= NN*SS*729) return;
    int n = idx / (SS*729);
    int r = idx - n*(SS*729);
    int s = r / 729;
    int uv = r - s*729;
    float sum = 0.f;
    #pragma unroll
    for (int ch = 0; ch < TCH; ++ch)
        sum += g_att_part[(((size_t)n*TCH + ch)*SS + s)*729 + uv];
    g_att[idx] = tanhf(sum * (1.0f/6400.f)) * alphas[s] + att0[s*729 + uv];
}

// ---------------------------------------------------------------------------
// Kernel C: xa = x@att ; h = lrelu(x + bn(W_out xa)) ; y2 = lrelu(x + bn(W_ff h))
// grid (50, NN), 256 threads, 2 sub-tiles of 4 t each, packed t-pairs.
// ---------------------------------------------------------------------------
__global__ void __launch_bounds__(256,1) k_main(const float* __restrict__ x,
        const float* __restrict__ W_out, const float* __restrict__ b_out,
        const float* __restrict__ g_out, const float* __restrict__ be_out,
        const float* __restrict__ m_out, const float* __restrict__ v_out,
        const float* __restrict__ W_ff,  const float* __restrict__ b_ff,
        const float* __restrict__ g_ff,  const float* __restrict__ be_ff,
        const float* __restrict__ m_ff,  const float* __restrict__ v_ff) {
    extern __shared__ ull smU[];
    ull* sWo2 = smU;            // 8192  (dup W_out, [j][o])
    ull* sWf2 = sWo2 + 8192;    // 4096  (dup W_ff,  [j][o])
    ull* sx2  = sWf2 + 4096;    // 3584  ([c][p][v] pairs)
    ull* sxa2 = sx2 + 3584;     // 7168  ([j][p][v] pairs; first 3584 reused for h)
    float* satt     = (float*)(sxa2 + 7168);  // 1458
    float* sscale_o = satt + 1458;
    float* sshift_o = sscale_o + 64;
    float* sscale_f = sshift_o + 64;
    float* sshift_f = sscale_f + 64;

    int n = blockIdx.y, tb = blockIdx.x;
    int tid = threadIdx.x, og = tid >> 5, vv = tid & 31;

    for (int i = tid; i < 8192; i += 256) {
        int o = i & 63, j = i >> 6;
        float w = W_out[o*128 + j];
        sWo2[i] = pk(w, w);
    }
    for (int i = tid; i < 4096; i += 256) {
        int o = i & 63, j = i >> 6;
        float w = W_ff[o*64 + j];
        sWf2[i] = pk(w, w);
    }
    for (int i = tid; i < 1458; i += 256) satt[i] = g_att[(size_t)n*1458 + i];
    if (tid < 64) {
        float sc = g_out[tid]*rsqrtf(v_out[tid]+EPSS);
        sscale_o[tid] = sc;
        sshift_o[tid] = be_out[tid] + sc*(b_out[tid]-m_out[tid]);
        float sf = g_ff[tid]*rsqrtf(v_ff[tid]+EPSS);
        sscale_f[tid] = sf;
        sshift_f[tid] = be_ff[tid] + sf*(b_ff[tid]-m_ff[tid]);
    }
    __syncthreads();

    for (int st = 0; st < 2; ++st) {
        int t0 = tb*8 + st*4;
        // stage x packed: sx2[(c*2+p)*28 + v] = {x[t0+2p], x[t0+2p+1]}
        for (int i = tid; i < 6912; i += 256) {
            int c = i / 108, r = i - c*108, tt = r / 27, v = r - tt*27;
            float val = x[(((size_t)n*64 + c)*400 + t0 + tt)*27 + v];
            ((float*)sx2)[2*((c*2 + (tt>>1))*28 + v) + (tt&1)] = val;
        }
        __syncthreads();

        // xa stage
        if (vv < 27) {
            int s = og >> 2, c0 = (og & 3)*16;
            ull ratt2[27];
            #pragma unroll
            for (int u = 0; u < 27; ++u) {
                float a = satt[s*729 + u*27 + vv];
                ratt2[u] = pk(a, a);
            }
            for (int ci = 0; ci < 16; ++ci) {
                int c = c0 + ci;
                ull a0 = 0, a1 = 0;
                #pragma unroll
                for (int u = 0; u < 27; ++u) {
                    a0 = fma2(sx2[(c*2)*28 + u],   ratt2[u], a0);
                    a1 = fma2(sx2[(c*2+1)*28 + u], ratt2[u], a1);
                }
                int j = s*64 + c;
                sxa2[(j*2)*28 + vv]   = a0;
                sxa2[(j*2+1)*28 + vv] = a1;
            }
        }
        __syncthreads();

        // W_out stage -> h (registers)
        ull h[8][2];
        if (vv < 27) {
            ull acc[8][2] = {};
            #pragma unroll 2
            for (int j = 0; j < 128; ++j) {
                ull a0 = sxa2[(j*2)*28 + vv], a1 = sxa2[(j*2+1)*28 + vv];
                const ull* wrow = sWo2 + j*64 + og*8;
                #pragma unroll
                for (int io = 0; io < 8; ++io) {
                    ull w2 = wrow[io];
                    acc[io][0] = fma2(w2, a0, acc[io][0]);
                    acc[io][1] = fma2(w2, a1, acc[io][1]);
                }
            }
            #pragma unroll
            for (int io = 0; io < 8; ++io) {
                int o = og*8+io;
                float sc = sscale_o[o], sh_ = sshift_o[o];
                #pragma unroll
                for (int p = 0; p < 2; ++p) {
                    float f0,f1,x0,x1;
                    upk(acc[io][p], f0, f1);
                    upk(sx2[(o*2+p)*28 + vv], x0, x1);
                    float v0 = x0 + f0*sc + sh_; v0 = fmaxf(v0, LEAKK*v0);
                    float v1 = x1 + f1*sc + sh_; v1 = fmaxf(v1, LEAKK*v1);
                    h[io][p] = pk(v0, v1);
                }
            }
        }
        __syncthreads();
        if (vv < 27) {
            #pragma unroll
            for (int io = 0; io < 8; ++io) {
                int o = og*8+io;
                sxa2[(o*2)*28 + vv]   = h[io][0];
                sxa2[(o*2+1)*28 + vv] = h[io][1];
            }
        }
        __syncthreads();

        // W_ff stage -> y2 (global)
        if (vv < 27) {
            ull acc[8][2] = {};
            #pragma unroll 2
            for (int j = 0; j < 64; ++j) {
                ull a0 = sxa2[(j*2)*28 + vv], a1 = sxa2[(j*2+1)*28 + vv];
                const ull* wrow = sWf2 + j*64 + og*8;
                #pragma unroll
                for (int io = 0; io < 8; ++io) {
                    ull w2 = wrow[io];
                    acc[io][0] = fma2(w2, a0, acc[io][0]);
                    acc[io][1] = fma2(w2, a1, acc[io][1]);
                }
            }
            #pragma unroll
            for (int io = 0; io < 8; ++io) {
                int o = og*8+io;
                float sc = sscale_f[o], sh_ = sshift_f[o];
                #pragma unroll
                for (int p = 0; p < 2; ++p) {
                    float f0,f1,x0,x1;
                    upk(acc[io][p], f0, f1);
                    upk(sx2[(o*2+p)*28 + vv], x0, x1);
                    float v0 = x0 + f0*sc + sh_; v0 = fmaxf(v0, LEAKK*v0);
                    float v1 = x1 + f1*sc + sh_; v1 = fmaxf(v1, LEAKK*v1);
                    g_y2[((size_t)n*400 + t0 + 2*p)*1792   + o*28 + vv] = v0;
                    g_y2[((size_t)n*400 + t0 + 2*p + 1)*1792 + o*28 + vv] = v1;
                }
            }
        }
        __syncthreads();
    }
}

// ---------------------------------------------------------------------------
// Kernel D: z = lrelu(y2 + bn(conv_t(y2) + b_t)); 8 t per block, packed pairs
// grid (50, NN), 256 threads
// ---------------------------------------------------------------------------
__global__ void __launch_bounds__(256,1) k_temporal(const float* __restrict__ W_t,
        const float* __restrict__ b_t, const float* __restrict__ g_t,
        const float* __restrict__ be_t, const float* __restrict__ m_t,
        const float* __restrict__ v_t, float* __restrict__ out) {
    extern __shared__ ull smU[];
    ull* sWt2 = smU;                        // 12288 (dup W_t, [(o*64+i)*3+tap])
    float* tile   = (float*)(sWt2 + 12288); // 10 * 1792
    float* sscale = tile + 17920;
    float* sshift = sscale + 64;

    int n = blockIdx.y, tb = blockIdx.x;
    int tid = threadIdx.x, og = tid >> 5, vv = tid & 31;

    for (int i = tid; i < 12288; i += 256) {
        float w = W_t[i];
        sWt2[i] = pk(w, w);
    }
    if (tid < 64) {
        float sc = g_t[tid]*rsqrtf(v_t[tid]+EPSS);
        sscale[tid] = sc;
        sshift[tid] = be_t[tid] + sc*(b_t[tid]-m_t[tid]);
    }
    int t0 = tb*8;
    for (int k = 0; k < 10; ++k) {
        int t = t0 - 1 + k;
        if (t >= 0 && t < 400) {
            const float* src = g_y2 + ((size_t)n*400 + t)*1792;
            for (int i = tid; i < 1792; i += 256) tile[k*1792 + i] = src[i];
        } else {
            for (int i = tid; i < 1792; i += 256) tile[k*1792 + i] = 0.f;
        }
    }
    __syncthreads();

    if (vv < 27) {
        ull acc[8][4] = {};
        #pragma unroll 2
        for (int i = 0; i < 64; ++i) {
            float a[10];
            #pragma unroll
            for (int k = 0; k < 10; ++k) a[k] = tile[k*1792 + i*28 + vv];
            ull pr[9];
            #pragma unroll
            for (int k = 0; k < 9; ++k) pr[k] = pk(a[k], a[k+1]);
            #pragma unroll
            for (int io = 0; io < 8; ++io) {
                const ull* w = sWt2 + ((og*8+io)*64 + i)*3;
                ull w0 = w[0], w1 = w[1], w2 = w[2];
                #pragma unroll
                for (int p = 0; p < 4; ++p) {
                    acc[io][p] = fma2(w0, pr[2*p],   acc[io][p]);
                    acc[io][p] = fma2(w1, pr[2*p+1], acc[io][p]);
                    acc[io][p] = fma2(w2, pr[2*p+2], acc[io][p]);
                }
            }
        }
        #pragma unroll
        for (int io = 0; io < 8; ++io) {
            int o = og*8+io;
            float sc = sscale[o], sh_ = sshift[o];
            size_t ob = ((size_t)n*64 + o)*400;
            #pragma unroll
            for (int p = 0; p < 4; ++p) {
                float f0,f1;
                upk(acc[io][p], f0, f1);
                float y0 = tile[(1+2*p)*1792 + o*28 + vv];
                float y1 = tile[(2+2*p)*1792 + o*28 + vv];
                float v0 = y0 + f0*sc + sh_; v0 = fmaxf(v0, LEAKK*v0);
                float v1 = y1 + f1*sc + sh_; v1 = fmaxf(v1, LEAKK*v1);
                out[(ob + t0 + 2*p)*27 + vv]     = v0;
                out[(ob + t0 + 2*p + 1)*27 + vv] = v1;
            }
        }
    }
}

// ---------------------------------------------------------------------------
extern "C" void kernel_launch(void* const* d_in, const int* in_sizes, int n_in,
                              void* d_out, int out_size) {
    const float* x      = (const float*)d_in[0];
    const float* pe     = (const float*)d_in[1];
    const float* W_in   = (const float*)d_in[2];
    const float* b_in   = (const float*)d_in[3];
    const float* alphas = (const float*)d_in[4];
    const float* att0   = (const float*)d_in[5];
    const float* W_out  = (const float*)d_in[6];
    const float* b_out  = (const float*)d_in[7];
    const float* g_out  = (const float*)d_in[8];
    const float* be_out = (const float*)d_in[9];
    const float* m_out  = (const float*)d_in[10];
    const float* v_out  = (const float*)d_in[11];
    const float* W_ff   = (const float*)d_in[12];
    const float* b_ff   = (const float*)d_in[13];
    const float* g_ff   = (const float*)d_in[14];
    const float* be_ff  = (const float*)d_in[15];
    const float* m_ff   = (const float*)d_in[16];
    const float* v_ff   = (const float*)d_in[17];
    const float* W_t    = (const float*)d_in[18];
    const float* b_t    = (const float*)d_in[19];
    const float* g_t    = (const float*)d_in[20];
    const float* be_t   = (const float*)d_in[21];
    const float* m_t    = (const float*)d_in[22];
    const float* v_t    = (const float*)d_in[23];
    float* out = (float*)d_out;

    const int smemA = 7680*8 + 64*4;                       // 61,696 B
    const int smemC = 23040*8 + (1458 + 256)*4;            // 191,176 B
    const int smemD = 12288*8 + (17920 + 128)*4;           // 170,496 B
    cudaFuncSetAttribute(k_att_part, cudaFuncAttributeMaxDynamicSharedMemorySize, smemA);
    cudaFuncSetAttribute(k_main,     cudaFuncAttributeMaxDynamicSharedMemorySize, smemC);
    cudaFuncSetAttribute(k_temporal, cudaFuncAttributeMaxDynamicSharedMemorySize, smemD);

    k_att_part<<<dim3(TCH, NN), 256, smemA>>>(x, pe, W_in, b_in);
    k_att_final<<<(NN*SS*729 + 255)/256, 256>>>(alphas, att0);
    k_main<<<dim3(TT/8, NN), 256, smemC>>>(x, W_out, b_out, g_out, be_out, m_out, v_out,
                                           W_ff, b_ff, g_ff, be_ff, m_ff, v_ff);
    k_temporal<<<dim3(TT/8, NN), 256, smemD>>>(W_t, b_t, g_t, be_t, m_t, v_t, out);
}

// round 8
// speedup vs baseline: 1.0133x; 1.0103x over previous
#include <cuda_runtime.h>

#define NN 32
#define CC 64
#define TT 400
#define VV 27
#define SS 2
#define ICC 16
#define OO 64
#define LEAKK 0.1f
#define EPSS 1e-5f

#define TCH 25            // t-chunks for kernel A (16 t each, 8 pairs)

typedef unsigned long long ull;

__device__ __forceinline__ ull fma2(ull a, ull b, ull c) {
    ull d;
    asm("fma.rn.f32x2 %0, %1, %2, %3;" : "=l"(d) : "l"(a), "l"(b), "l"(c));
    return d;
}
__device__ __forceinline__ ull pk(float lo, float hi) {
    ull r;
    asm("mov.b64 %0, {%1, %2};" : "=l"(r) : "f"(lo), "f"(hi));
    return r;
}
__device__ __forceinline__ void upk(ull v, float& lo, float& hi) {
    asm("mov.b64 {%0, %1}, %2;" : "=f"(lo), "=f"(hi) : "l"(v));
}

// Scratch (static device globals — allocation-free)
__device__ float g_att_part[NN*TCH*SS*VV*VV];
__device__ float g_att[NN*SS*VV*VV];
__device__ float g_y2[(size_t)NN*TT*1792];      // [n][t][c*28+v], padded

// ---------------------------------------------------------------------------
// Kernel A: y = x + pe ; qk = W_in*y + b_in ; partial att accum over 16 t
// grid (25, NN), 512 threads (16 og x 4 outputs). Packed over t-pairs.
// ---------------------------------------------------------------------------
__global__ void __launch_bounds__(512,1) k_att_part(const float* __restrict__ x,
                                                    const float* __restrict__ pe,
                                                    const float* __restrict__ W_in,
                                                    const float* __restrict__ b_in) {
    extern __shared__ ull smU[];
    ull* sW2  = smU;            // 4096  (dup W_in, [c][o])
    ull* sy2  = sW2 + 4096;     // 1792  ([c][v] t-pair)
    ull* sqk2 = sy2 + 1792;     // 1792  ([o][v] t-pair)
    float* sb = (float*)(sqk2 + 1792);  // 64

    int n = blockIdx.y, chunk = blockIdx.x;
    int tid = threadIdx.x, og = tid >> 5, vv = tid & 31;

    for (int i = tid; i < 4096; i += 512) {
        int o = i & 63, c = i >> 6;
        float w = W_in[o*64 + c];
        sW2[i] = pk(w, w);
    }
    if (tid < 64) sb[tid] = b_in[tid];

    // att tiles: 2 s * 14 u2 * 14 v2 = 392 tiles of 2x2 (u,v); one per thread
    ull accA[4] = {0,0,0,0};
    int tileA = tid;                 // valid < 392
    int sA = tileA / 196; int rA = tileA - sA*196;
    int uA = (rA/14)*2, vA = (rA%14)*2;

    __syncthreads();

    for (int it = 0; it < 8; ++it) {
        int t0 = chunk*16 + it*2;
        for (int i = tid; i < 3456; i += 512) {
            int c = i / 54, r = i - c*54, tt = r / 27, v = r - tt*27;
            float val = x[(((size_t)n*64 + c)*400 + t0 + tt)*27 + v]
                      + pe[((size_t)c*400 + t0 + tt)*27 + v];
            ((float*)sy2)[2*(c*28 + v) + tt] = val;
        }
        __syncthreads();

        // projection: qk[o][vv] packed pair; 4 outputs per thread
        if (vv < 27) {
            ull acc[4];
            #pragma unroll
            for (int io = 0; io < 4; ++io) { float b = sb[og*4+io]; acc[io] = pk(b, b); }
            #pragma unroll 4
            for (int c = 0; c < 64; ++c) {
                ull yp = sy2[c*28 + vv];
                const ull* wrow = sW2 + c*64 + og*4;
                #pragma unroll
                for (int io = 0; io < 4; ++io)
                    acc[io] = fma2(wrow[io], yp, acc[io]);
            }
            #pragma unroll
            for (int io = 0; io < 4; ++io) sqk2[(og*4+io)*28 + vv] = acc[io];
        } else if (vv == 27) {
            // zero pad column so u+1 / v+1 loads are safe
            #pragma unroll
            for (int io = 0; io < 4; ++io) sqk2[(og*4+io)*28 + 27] = 0ULL;
        }
        __syncthreads();

        // q.k per 2x2 (u,v) tile, both t of the pair live in the two halves
        if (tileA < 392) {
            const ull* q  = sqk2 + (sA*16)*28;
            const ull* kk = sqk2 + (32 + sA*16)*28;
            #pragma unroll 4
            for (int c = 0; c < 16; ++c) {
                ull q0 = q[c*28+uA],  q1 = q[c*28+uA+1];
                ull k0 = kk[c*28+vA], k1 = kk[c*28+vA+1];
                accA[0] = fma2(q0,k0,accA[0]); accA[1] = fma2(q0,k1,accA[1]);
                accA[2] = fma2(q1,k0,accA[2]); accA[3] = fma2(q1,k1,accA[3]);
            }
        }
        __syncthreads();
    }

    // horizontal-reduce pairs and store partials
    if (tileA < 392) {
        float* base = g_att_part + (((size_t)n*TCH + chunk)*SS + sA)*729;
        float a0,b0; upk(accA[0],a0,b0); base[uA*27+vA] = a0+b0;
        float a1,b1; upk(accA[1],a1,b1);
        float a2,b2; upk(accA[2],a2,b2);
        float a3,b3; upk(accA[3],a3,b3);
        if (vA+1 < 27)              base[uA*27+vA+1]     = a1+b1;
        if (uA+1 < 27)              base[(uA+1)*27+vA]   = a2+b2;
        if (uA+1 < 27 && vA+1 < 27) base[(uA+1)*27+vA+1] = a3+b3;
    }
}

// ---------------------------------------------------------------------------
// Kernel B: reduce chunks + tanh/alpha/att0
// ---------------------------------------------------------------------------
__global__ void __launch_bounds__(256) k_att_final(const float* __restrict__ alphas,
                                                   const float* __restrict__ att0) {
    int idx = blockIdx.x*256 + threadIdx.x;
    if (idx >= NN*SS*729) return;
    int n = idx / (SS*729);
    int r = idx - n*(SS*729);
    int s = r / 729;
    int uv = r - s*729;
    float sum = 0.f;
    #pragma unroll
    for (int ch = 0; ch < TCH; ++ch)
        sum += g_att_part[(((size_t)n*TCH + ch)*SS + s)*729 + uv];
    g_att[idx] = tanhf(sum * (1.0f/6400.f)) * alphas[s] + att0[s*729 + uv];
}

// ---------------------------------------------------------------------------
// Kernel C: xa = x@att ; h = lrelu(x + bn(W_out xa)) ; y2 = lrelu(x + bn(W_ff h))
// grid (50, NN), 512 threads, 2 sub-tiles of 4 t each, packed t-pairs.
// ---------------------------------------------------------------------------
__global__ void __launch_bounds__(512,1) k_main(const float* __restrict__ x,
        const float* __restrict__ W_out, const float* __restrict__ b_out,
        const float* __restrict__ g_out, const float* __restrict__ be_out,
        const float* __restrict__ m_out, const float* __restrict__ v_out,
        const float* __restrict__ W_ff,  const float* __restrict__ b_ff,
        const float* __restrict__ g_ff,  const float* __restrict__ be_ff,
        const float* __restrict__ m_ff,  const float* __restrict__ v_ff) {
    extern __shared__ ull smU[];
    ull* sWo2 = smU;            // 8192  (dup W_out, [j][o])
    ull* sWf2 = sWo2 + 8192;    // 4096  (dup W_ff,  [j][o])
    ull* sx2  = sWf2 + 4096;    // 3584  ([c][p][v] pairs)
    ull* sxa2 = sx2 + 3584;     // 7168  ([j][p][v] pairs; first 3584 reused for h)
    float* satt     = (float*)(sxa2 + 7168);  // 1458
    float* sscale_o = satt + 1458;
    float* sshift_o = sscale_o + 64;
    float* sscale_f = sshift_o + 64;
    float* sshift_f = sscale_f + 64;

    int n = blockIdx.y, tb = blockIdx.x;
    int tid = threadIdx.x, og = tid >> 5, vv = tid & 31;

    for (int i = tid; i < 8192; i += 512) {
        int o = i & 63, j = i >> 6;
        float w = W_out[o*128 + j];
        sWo2[i] = pk(w, w);
    }
    for (int i = tid; i < 4096; i += 512) {
        int o = i & 63, j = i >> 6;
        float w = W_ff[o*64 + j];
        sWf2[i] = pk(w, w);
    }
    for (int i = tid; i < 1458; i += 512) satt[i] = g_att[(size_t)n*1458 + i];
    if (tid < 64) {
        float sc = g_out[tid]*rsqrtf(v_out[tid]+EPSS);
        sscale_o[tid] = sc;
        sshift_o[tid] = be_out[tid] + sc*(b_out[tid]-m_out[tid]);
        float sf = g_ff[tid]*rsqrtf(v_ff[tid]+EPSS);
        sscale_f[tid] = sf;
        sshift_f[tid] = be_ff[tid] + sf*(b_ff[tid]-m_ff[tid]);
    }
    __syncthreads();

    for (int st = 0; st < 2; ++st) {
        int t0 = tb*8 + st*4;
        // stage x packed: sx2[(c*2+p)*28 + v] = {x[t0+2p], x[t0+2p+1]}
        for (int i = tid; i < 6912; i += 512) {
            int c = i / 108, r = i - c*108, tt = r / 27, v = r - tt*27;
            float val = x[(((size_t)n*64 + c)*400 + t0 + tt)*27 + v];
            ((float*)sx2)[2*((c*2 + (tt>>1))*28 + v) + (tt&1)] = val;
        }
        __syncthreads();

        // xa stage: 8 c per og; att load per-lane, x loads warp-uniform bcast
        if (vv < 27) {
            int s = og >> 3, c0 = (og & 7)*8;
            ull a0[8] = {}, a1[8] = {};
            #pragma unroll 3
            for (int u = 0; u < 27; ++u) {
                float av = satt[s*729 + u*27 + vv];
                ull av2 = pk(av, av);
                #pragma unroll
                for (int ci = 0; ci < 8; ++ci) {
                    int c = c0 + ci;
                    a0[ci] = fma2(sx2[(c*2)*28 + u],   av2, a0[ci]);
                    a1[ci] = fma2(sx2[(c*2+1)*28 + u], av2, a1[ci]);
                }
            }
            #pragma unroll
            for (int ci = 0; ci < 8; ++ci) {
                int j = s*64 + c0 + ci;
                sxa2[(j*2)*28 + vv]   = a0[ci];
                sxa2[(j*2+1)*28 + vv] = a1[ci];
            }
        }
        __syncthreads();

        // W_out stage -> h (registers); 4 outputs per thread
        ull h[4][2];
        if (vv < 27) {
            ull acc[4][2] = {};
            #pragma unroll 4
            for (int j = 0; j < 128; ++j) {
                ull a0 = sxa2[(j*2)*28 + vv], a1 = sxa2[(j*2+1)*28 + vv];
                const ull* wrow = sWo2 + j*64 + og*4;
                #pragma unroll
                for (int io = 0; io < 4; ++io) {
                    ull w2 = wrow[io];
                    acc[io][0] = fma2(w2, a0, acc[io][0]);
                    acc[io][1] = fma2(w2, a1, acc[io][1]);
                }
            }
            #pragma unroll
            for (int io = 0; io < 4; ++io) {
                int o = og*4+io;
                float sc = sscale_o[o], sh_ = sshift_o[o];
                #pragma unroll
                for (int p = 0; p < 2; ++p) {
                    float f0,f1,x0,x1;
                    upk(acc[io][p], f0, f1);
                    upk(sx2[(o*2+p)*28 + vv], x0, x1);
                    float v0 = x0 + f0*sc + sh_; v0 = fmaxf(v0, LEAKK*v0);
                    float v1 = x1 + f1*sc + sh_; v1 = fmaxf(v1, LEAKK*v1);
                    h[io][p] = pk(v0, v1);
                }
            }
        }
        __syncthreads();
        if (vv < 27) {
            #pragma unroll
            for (int io = 0; io < 4; ++io) {
                int o = og*4+io;
                sxa2[(o*2)*28 + vv]   = h[io][0];
                sxa2[(o*2+1)*28 + vv] = h[io][1];
            }
        }
        __syncthreads();

        // W_ff stage -> y2 (global)
        if (vv < 27) {
            ull acc[4][2] = {};
            #pragma unroll 4
            for (int j = 0; j < 64; ++j) {
                ull a0 = sxa2[(j*2)*28 + vv], a1 = sxa2[(j*2+1)*28 + vv];
                const ull* wrow = sWf2 + j*64 + og*4;
                #pragma unroll
                for (int io = 0; io < 4; ++io) {
                    ull w2 = wrow[io];
                    acc[io][0] = fma2(w2, a0, acc[io][0]);
                    acc[io][1] = fma2(w2, a1, acc[io][1]);
                }
            }
            #pragma unroll
            for (int io = 0; io < 4; ++io) {
                int o = og*4+io;
                float sc = sscale_f[o], sh_ = sshift_f[o];
                #pragma unroll
                for (int p = 0; p < 2; ++p) {
                    float f0,f1,x0,x1;
                    upk(acc[io][p], f0, f1);
                    upk(sx2[(o*2+p)*28 + vv], x0, x1);
                    float v0 = x0 + f0*sc + sh_; v0 = fmaxf(v0, LEAKK*v0);
                    float v1 = x1 + f1*sc + sh_; v1 = fmaxf(v1, LEAKK*v1);
                    g_y2[((size_t)n*400 + t0 + 2*p)*1792   + o*28 + vv] = v0;
                    g_y2[((size_t)n*400 + t0 + 2*p + 1)*1792 + o*28 + vv] = v1;
                }
            }
        }
        __syncthreads();
    }
}

// ---------------------------------------------------------------------------
// Kernel D: z = lrelu(y2 + bn(conv_t(y2) + b_t)); 8 t per block, packed pairs
// grid (50, NN), 512 threads (16 og x 4 outputs)
// ---------------------------------------------------------------------------
__global__ void __launch_bounds__(512,1) k_temporal(const float* __restrict__ W_t,
        const float* __restrict__ b_t, const float* __restrict__ g_t,
        const float* __restrict__ be_t, const float* __restrict__ m_t,
        const float* __restrict__ v_t, float* __restrict__ out) {
    extern __shared__ ull smU[];
    ull* sWt2 = smU;                        // 12288 (dup W_t, [(o*64+i)*3+tap])
    float* tile   = (float*)(sWt2 + 12288); // 10 * 1792
    float* sscale = tile + 17920;
    float* sshift = sscale + 64;

    int n = blockIdx.y, tb = blockIdx.x;
    int tid = threadIdx.x, og = tid >> 5, vv = tid & 31;

    for (int i = tid; i < 12288; i += 512) {
        float w = W_t[i];
        sWt2[i] = pk(w, w);
    }
    if (tid < 64) {
        float sc = g_t[tid]*rsqrtf(v_t[tid]+EPSS);
        sscale[tid] = sc;
        sshift[tid] = be_t[tid] + sc*(b_t[tid]-m_t[tid]);
    }
    int t0 = tb*8;
    for (int k = 0; k < 10; ++k) {
        int t = t0 - 1 + k;
        if (t >= 0 && t < 400) {
            const float* src = g_y2 + ((size_t)n*400 + t)*1792;
            for (int i = tid; i < 1792; i += 512) tile[k*1792 + i] = src[i];
        } else {
            for (int i = tid; i < 1792; i += 512) tile[k*1792 + i] = 0.f;
        }
    }
    __syncthreads();

    if (vv < 27) {
        ull acc[4][4] = {};
        #pragma unroll 4
        for (int i = 0; i < 64; ++i) {
            float a[10];
            #pragma unroll
            for (int k = 0; k < 10; ++k) a[k] = tile[k*1792 + i*28 + vv];
            ull pr[9];
            #pragma unroll
            for (int k = 0; k < 9; ++k) pr[k] = pk(a[k], a[k+1]);
            #pragma unroll
            for (int io = 0; io < 4; ++io) {
                const ull* w = sWt2 + ((og*4+io)*64 + i)*3;
                ull w0 = w[0], w1 = w[1], w2 = w[2];
                #pragma unroll
                for (int p = 0; p < 4; ++p) {
                    acc[io][p] = fma2(w0, pr[2*p],   acc[io][p]);
                    acc[io][p] = fma2(w1, pr[2*p+1], acc[io][p]);
                    acc[io][p] = fma2(w2, pr[2*p+2], acc[io][p]);
                }
            }
        }
        #pragma unroll
        for (int io = 0; io < 4; ++io) {
            int o = og*4+io;
            float sc = sscale[o], sh_ = sshift[o];
            size_t ob = ((size_t)n*64 + o)*400;
            #pragma unroll
            for (int p = 0; p < 4; ++p) {
                float f0,f1;
                upk(acc[io][p], f0, f1);
                float y0 = tile[(1+2*p)*1792 + o*28 + vv];
                float y1 = tile[(2+2*p)*1792 + o*28 + vv];
                float v0 = y0 + f0*sc + sh_; v0 = fmaxf(v0, LEAKK*v0);
                float v1 = y1 + f1*sc + sh_; v1 = fmaxf(v1, LEAKK*v1);
                out[(ob + t0 + 2*p)*27 + vv]     = v0;
                out[(ob + t0 + 2*p + 1)*27 + vv] = v1;
            }
        }
    }
}

// ---------------------------------------------------------------------------
extern "C" void kernel_launch(void* const* d_in, const int* in_sizes, int n_in,
                              void* d_out, int out_size) {
    const float* x      = (const float*)d_in[0];
    const float* pe     = (const float*)d_in[1];
    const float* W_in   = (const float*)d_in[2];
    const float* b_in   = (const float*)d_in[3];
    const float* alphas = (const float*)d_in[4];
    const float* att0   = (const float*)d_in[5];
    const float* W_out  = (const float*)d_in[6];
    const float* b_out  = (const float*)d_in[7];
    const float* g_out  = (const float*)d_in[8];
    const float* be_out = (const float*)d_in[9];
    const float* m_out  = (const float*)d_in[10];
    const float* v_out  = (const float*)d_in[11];
    const float* W_ff   = (const float*)d_in[12];
    const float* b_ff   = (const float*)d_in[13];
    const float* g_ff   = (const float*)d_in[14];
    const float* be_ff  = (const float*)d_in[15];
    const float* m_ff   = (const float*)d_in[16];
    const float* v_ff   = (const float*)d_in[17];
    const float* W_t    = (const float*)d_in[18];
    const float* b_t    = (const float*)d_in[19];
    const float* g_t    = (const float*)d_in[20];
    const float* be_t   = (const float*)d_in[21];
    const float* m_t    = (const float*)d_in[22];
    const float* v_t    = (const float*)d_in[23];
    float* out = (float*)d_out;

    const int smemA = 7680*8 + 64*4;                       // 61,696 B
    const int smemC = 23040*8 + (1458 + 256)*4;            // 191,176 B
    const int smemD = 12288*8 + (17920 + 128)*4;           // 170,496 B
    cudaFuncSetAttribute(k_att_part, cudaFuncAttributeMaxDynamicSharedMemorySize, smemA);
    cudaFuncSetAttribute(k_main,     cudaFuncAttributeMaxDynamicSharedMemorySize, smemC);
    cudaFuncSetAttribute(k_temporal, cudaFuncAttributeMaxDynamicSharedMemorySize, smemD);

    k_att_part<<<dim3(TCH, NN), 512, smemA>>>(x, pe, W_in, b_in);
    k_att_final<<<(NN*SS*729 + 255)/256, 256>>>(alphas, att0);
    k_main<<<dim3(TT/8, NN), 512, smemC>>>(x, W_out, b_out, g_out, be_out, m_out, v_out,
                                           W_ff, b_ff, g_ff, be_ff, m_ff, v_ff);
    k_temporal<<<dim3(TT/8, NN), 512, smemD>>>(W_t, b_t, g_t, be_t, m_t, v_t, out);
}

// round 9
// speedup vs baseline: 1.0624x; 1.0485x over previous
#include <cuda_runtime.h>

#define NN 32
#define CC 64
#define TT 400
#define VV 27
#define SS 2
#define OO 64
#define LEAKK 0.1f
#define EPSS 1e-5f

#define TCH 25            // t-chunks for kernel A (16 t each, 8 pairs)

typedef unsigned long long ull;

__device__ __forceinline__ ull fma2(ull a, ull b, ull c) {
    ull d;
    asm("fma.rn.f32x2 %0, %1, %2, %3;" : "=l"(d) : "l"(a), "l"(b), "l"(c));
    return d;
}
__device__ __forceinline__ ull pk(float lo, float hi) {
    ull r;
    asm("mov.b64 %0, {%1, %2};" : "=l"(r) : "f"(lo), "f"(hi));
    return r;
}
__device__ __forceinline__ void upk(ull v, float& lo, float& hi) {
    asm("mov.b64 {%0, %1}, %2;" : "=f"(lo), "=f"(hi) : "l"(v));
}

// Scratch (static device globals — allocation-free)
__device__ float g_att_part[NN*TCH*SS*VV*VV];
__device__ float g_att[NN*SS*VV*VV];
__device__ float g_y2[(size_t)NN*TT*1792];      // [n][t][c*28+v], padded

// ---------------------------------------------------------------------------
// Kernel A: y = x + pe ; qk = W_in*y + b_in ; partial att accum over 16 t
// grid (25, NN), 512 threads (16 og x 4 outputs). Packed over t-pairs.
// ---------------------------------------------------------------------------
__global__ void __launch_bounds__(512,2) k_att_part(const float* __restrict__ x,
                                                    const float* __restrict__ pe,
                                                    const float* __restrict__ W_in,
                                                    const float* __restrict__ b_in) {
    extern __shared__ ull smU[];
    ull* sW2  = smU;            // 4096  (dup W_in, [c][o])
    ull* sy2  = sW2 + 4096;     // 1792  ([c][v] t-pair)
    ull* sqk2 = sy2 + 1792;     // 1792  ([o][v] t-pair)
    float* sb = (float*)(sqk2 + 1792);  // 64

    int n = blockIdx.y, chunk = blockIdx.x;
    int tid = threadIdx.x, og = tid >> 5, vv = tid & 31;

    for (int i = tid; i < 4096; i += 512) {
        int o = i & 63, c = i >> 6;
        float w = W_in[o*64 + c];
        sW2[i] = pk(w, w);
    }
    if (tid < 64) sb[tid] = b_in[tid];

    // att tiles: 2 s * 14 u2 * 14 v2 = 392 tiles of 2x2 (u,v); one per thread
    ull accA[4] = {0,0,0,0};
    int tileA = tid;                 // valid < 392
    int sA = tileA / 196; int rA = tileA - sA*196;
    int uA = (rA/14)*2, vA = (rA%14)*2;

    __syncthreads();

    for (int it = 0; it < 8; ++it) {
        int t0 = chunk*16 + it*2;
        for (int i = tid; i < 3456; i += 512) {
            int c = i / 54, r = i - c*54, tt = r / 27, v = r - tt*27;
            float val = x[(((size_t)n*64 + c)*400 + t0 + tt)*27 + v]
                      + pe[((size_t)c*400 + t0 + tt)*27 + v];
            ((float*)sy2)[2*(c*28 + v) + tt] = val;
        }
        __syncthreads();

        // projection: qk[o][vv] packed pair; 4 outputs per thread
        if (vv < 27) {
            ull acc[4];
            #pragma unroll
            for (int io = 0; io < 4; ++io) { float b = sb[og*4+io]; acc[io] = pk(b, b); }
            #pragma unroll 4
            for (int c = 0; c < 64; ++c) {
                ull yp = sy2[c*28 + vv];
                const ull* wrow = sW2 + c*64 + og*4;
                #pragma unroll
                for (int io = 0; io < 4; ++io)
                    acc[io] = fma2(wrow[io], yp, acc[io]);
            }
            #pragma unroll
            for (int io = 0; io < 4; ++io) sqk2[(og*4+io)*28 + vv] = acc[io];
        } else if (vv == 27) {
            // zero pad column so u+1 / v+1 loads are safe
            #pragma unroll
            for (int io = 0; io < 4; ++io) sqk2[(og*4+io)*28 + 27] = 0ULL;
        }
        __syncthreads();

        // q.k per 2x2 (u,v) tile, both t of the pair live in the two halves
        if (tileA < 392) {
            const ull* q  = sqk2 + (sA*16)*28;
            const ull* kk = sqk2 + (32 + sA*16)*28;
            #pragma unroll 4
            for (int c = 0; c < 16; ++c) {
                ull q0 = q[c*28+uA],  q1 = q[c*28+uA+1];
                ull k0 = kk[c*28+vA], k1 = kk[c*28+vA+1];
                accA[0] = fma2(q0,k0,accA[0]); accA[1] = fma2(q0,k1,accA[1]);
                accA[2] = fma2(q1,k0,accA[2]); accA[3] = fma2(q1,k1,accA[3]);
            }
        }
        __syncthreads();
    }

    // horizontal-reduce pairs and store partials
    if (tileA < 392) {
        float* base = g_att_part + (((size_t)n*TCH + chunk)*SS + sA)*729;
        float a0,b0; upk(accA[0],a0,b0); base[uA*27+vA] = a0+b0;
        float a1,b1; upk(accA[1],a1,b1);
        float a2,b2; upk(accA[2],a2,b2);
        float a3,b3; upk(accA[3],a3,b3);
        if (vA+1 < 27)              base[uA*27+vA+1]     = a1+b1;
        if (uA+1 < 27)              base[(uA+1)*27+vA]   = a2+b2;
        if (uA+1 < 27 && vA+1 < 27) base[(uA+1)*27+vA+1] = a3+b3;
    }
}

// ---------------------------------------------------------------------------
// Kernel B: reduce chunks + tanh/alpha/att0
// ---------------------------------------------------------------------------
__global__ void __launch_bounds__(256) k_att_final(const float* __restrict__ alphas,
                                                   const float* __restrict__ att0) {
    int idx = blockIdx.x*256 + threadIdx.x;
    if (idx >= NN*SS*729) return;
    int n = idx / (SS*729);
    int r = idx - n*(SS*729);
    int s = r / 729;
    int uv = r - s*729;
    float sum = 0.f;
    #pragma unroll
    for (int ch = 0; ch < TCH; ++ch)
        sum += g_att_part[(((size_t)n*TCH + ch)*SS + s)*729 + uv];
    g_att[idx] = tanhf(sum * (1.0f/6400.f)) * alphas[s] + att0[s*729 + uv];
}

// ---------------------------------------------------------------------------
// Kernel C: xa = x@att ; h = lrelu(x + bn(W_out xa)) ; y2 = lrelu(x + bn(W_ff h))
// grid (200, NN), 512 threads, 2 t per block. Weights packed over o-pairs
// (no duplication); xa stage packed over the t-pair; W stages o-packed.
// ---------------------------------------------------------------------------
__global__ void __launch_bounds__(512,2) k_main(const float* __restrict__ x,
        const float* __restrict__ W_out, const float* __restrict__ b_out,
        const float* __restrict__ g_out, const float* __restrict__ be_out,
        const float* __restrict__ m_out, const float* __restrict__ v_out,
        const float* __restrict__ W_ff,  const float* __restrict__ b_ff,
        const float* __restrict__ g_ff,  const float* __restrict__ be_ff,
        const float* __restrict__ m_ff,  const float* __restrict__ v_ff) {
    extern __shared__ ull smU[];
    ull* sWoP = smU;                      // 4096  ([j][op] pk{W[2op][j],W[2op+1][j]})
    ull* sWfP = sWoP + 4096;              // 2048
    ull* sx2  = sWfP + 2048;              // 1792  ([c][u] t-pair {t0,t1})
    float* sxaF = (float*)(sx2 + 1792);   // 7168  ([j][tt][v] scalars; reused for h)
    float* satt = sxaF + 7168;            // 1458
    float* sscale_o = satt + 1458;
    float* sshift_o = sscale_o + 64;
    float* sscale_f = sshift_o + 64;
    float* sshift_f = sscale_f + 64;

    int n = blockIdx.y, tb = blockIdx.x;
    int tid = threadIdx.x, og = tid >> 5, vv = tid & 31;
    int t0 = tb*2;

    for (int idx = tid; idx < 4096; idx += 512) {
        int op = idx & 31, j = idx >> 5;
        sWoP[idx] = pk(W_out[(2*op)*128 + j], W_out[(2*op+1)*128 + j]);
    }
    for (int idx = tid; idx < 2048; idx += 512) {
        int op = idx & 31, j = idx >> 5;
        sWfP[idx] = pk(W_ff[(2*op)*64 + j], W_ff[(2*op+1)*64 + j]);
    }
    for (int i = tid; i < 1458; i += 512) satt[i] = g_att[(size_t)n*1458 + i];
    if (tid < 64) {
        float sc = g_out[tid]*rsqrtf(v_out[tid]+EPSS);
        sscale_o[tid] = sc;
        sshift_o[tid] = be_out[tid] + sc*(b_out[tid]-m_out[tid]);
        float sf = g_ff[tid]*rsqrtf(v_ff[tid]+EPSS);
        sscale_f[tid] = sf;
        sshift_f[tid] = be_ff[tid] + sf*(b_ff[tid]-m_ff[tid]);
    }
    // stage x packed over the t-pair: sx2[c*28+u] = {x[t0], x[t0+1]}
    for (int i = tid; i < 3456; i += 512) {
        int c = i / 54, r = i - c*54, tt = r / 27, u = r - tt*27;
        ((float*)sx2)[2*(c*28+u) + tt] = x[(((size_t)n*64 + c)*400 + t0 + tt)*27 + u];
    }
    __syncthreads();

    // xa stage: t-packed; x loads warp-uniform, att per-lane
    if (vv < 27) {
        int s = og >> 3, c0 = (og & 7)*8;
        ull a[8] = {};
        #pragma unroll 3
        for (int u = 0; u < 27; ++u) {
            float av = satt[s*729 + u*27 + vv];
            ull av2 = pk(av, av);
            #pragma unroll
            for (int ci = 0; ci < 8; ++ci)
                a[ci] = fma2(sx2[(c0+ci)*28 + u], av2, a[ci]);
        }
        #pragma unroll
        for (int ci = 0; ci < 8; ++ci) {
            int j = s*64 + c0 + ci;
            float f0, f1; upk(a[ci], f0, f1);
            sxaF[(j*2)*28 + vv]   = f0;
            sxaF[(j*2+1)*28 + vv] = f1;
        }
    }
    __syncthreads();

    // W_out stage: o-packed accumulators acc[opl][tt]
    float hv[2][2][2];   // [opl][tt][even/odd o]
    {
        ull acc[2][2] = {};
        if (vv < 27) {
            #pragma unroll 4
            for (int j = 0; j < 128; ++j) {
                float a0 = sxaF[(j*2)*28 + vv], a1 = sxaF[(j*2+1)*28 + vv];
                ull b0 = pk(a0, a0), b1 = pk(a1, a1);
                ull w0 = sWoP[j*32 + og*2], w1 = sWoP[j*32 + og*2 + 1];
                acc[0][0] = fma2(w0, b0, acc[0][0]);
                acc[0][1] = fma2(w0, b1, acc[0][1]);
                acc[1][0] = fma2(w1, b0, acc[1][0]);
                acc[1][1] = fma2(w1, b1, acc[1][1]);
            }
            #pragma unroll
            for (int opl = 0; opl < 2; ++opl) {
                int o0 = og*4 + opl*2;
                float sc0 = sscale_o[o0],   sh0 = sshift_o[o0];
                float sc1 = sscale_o[o0+1], sh1 = sshift_o[o0+1];
                #pragma unroll
                for (int tt = 0; tt < 2; ++tt) {
                    float f0, f1; upk(acc[opl][tt], f0, f1);
                    float x0 = ((float*)sx2)[2*(o0*28+vv) + tt];
                    float x1 = ((float*)sx2)[2*((o0+1)*28+vv) + tt];
                    float v0 = x0 + f0*sc0 + sh0; v0 = fmaxf(v0, LEAKK*v0);
                    float v1 = x1 + f1*sc1 + sh1; v1 = fmaxf(v1, LEAKK*v1);
                    hv[opl][tt][0] = v0; hv[opl][tt][1] = v1;
                }
            }
        }
    }
    __syncthreads();          // all sxa reads done
    if (vv < 27) {
        #pragma unroll
        for (int opl = 0; opl < 2; ++opl) {
            int o0 = og*4 + opl*2;
            #pragma unroll
            for (int tt = 0; tt < 2; ++tt) {
                sxaF[(o0*2+tt)*28 + vv]     = hv[opl][tt][0];
                sxaF[((o0+1)*2+tt)*28 + vv] = hv[opl][tt][1];
            }
        }
    }
    __syncthreads();

    // W_ff stage -> y2 (global)
    if (vv < 27) {
        ull acc[2][2] = {};
        #pragma unroll 4
        for (int j = 0; j < 64; ++j) {
            float a0 = sxaF[(j*2)*28 + vv], a1 = sxaF[(j*2+1)*28 + vv];
            ull b0 = pk(a0, a0), b1 = pk(a1, a1);
            ull w0 = sWfP[j*32 + og*2], w1 = sWfP[j*32 + og*2 + 1];
            acc[0][0] = fma2(w0, b0, acc[0][0]);
            acc[0][1] = fma2(w0, b1, acc[0][1]);
            acc[1][0] = fma2(w1, b0, acc[1][0]);
            acc[1][1] = fma2(w1, b1, acc[1][1]);
        }
        #pragma unroll
        for (int opl = 0; opl < 2; ++opl) {
            int o0 = og*4 + opl*2;
            float sc0 = sscale_f[o0],   sh0 = sshift_f[o0];
            float sc1 = sscale_f[o0+1], sh1 = sshift_f[o0+1];
            #pragma unroll
            for (int tt = 0; tt < 2; ++tt) {
                float f0, f1; upk(acc[opl][tt], f0, f1);
                float x0 = ((float*)sx2)[2*(o0*28+vv) + tt];
                float x1 = ((float*)sx2)[2*((o0+1)*28+vv) + tt];
                float v0 = x0 + f0*sc0 + sh0; v0 = fmaxf(v0, LEAKK*v0);
                float v1 = x1 + f1*sc1 + sh1; v1 = fmaxf(v1, LEAKK*v1);
                size_t row = (size_t)(n*400 + t0 + tt)*1792;
                g_y2[row + o0*28 + vv]     = v0;
                g_y2[row + (o0+1)*28 + vv] = v1;
            }
        }
    }
}

// ---------------------------------------------------------------------------
// Kernel D: z = lrelu(y2 + bn(conv_t(y2) + b_t)); 4 t per block, o-packed.
// grid (100, NN), 512 threads (16 og x 2 opairs x 4 t)
// ---------------------------------------------------------------------------
__global__ void __launch_bounds__(512,2) k_temporal(const float* __restrict__ W_t,
        const float* __restrict__ b_t, const float* __restrict__ g_t,
        const float* __restrict__ be_t, const float* __restrict__ m_t,
        const float* __restrict__ v_t, float* __restrict__ out) {
    extern __shared__ ull smU[];
    ull* sWtP = smU;                        // 6144  ([(i*3+tap)][op] o-pairs)
    float* tile   = (float*)(sWtP + 6144);  // 6 * 1792
    float* sscale = tile + 6*1792;
    float* sshift = sscale + 64;

    int n = blockIdx.y, tb = blockIdx.x;
    int tid = threadIdx.x, og = tid >> 5, vv = tid & 31;
    int t0 = tb*4;

    for (int idx = tid; idx < 6144; idx += 512) {
        int op = idx & 31, r = idx >> 5;     // r = i*3+tap
        sWtP[idx] = pk(W_t[(2*op)*192 + r], W_t[(2*op+1)*192 + r]);
    }
    if (tid < 64) {
        float sc = g_t[tid]*rsqrtf(v_t[tid]+EPSS);
        sscale[tid] = sc;
        sshift[tid] = be_t[tid] + sc*(b_t[tid]-m_t[tid]);
    }
    #pragma unroll
    for (int k = 0; k < 6; ++k) {
        int t = t0 - 1 + k;
        if (t >= 0 && t < 400) {
            const float* src = g_y2 + ((size_t)n*400 + t)*1792;
            for (int i = tid; i < 1792; i += 512) tile[k*1792 + i] = src[i];
        } else {
            for (int i = tid; i < 1792; i += 512) tile[k*1792 + i] = 0.f;
        }
    }
    __syncthreads();

    if (vv < 27) {
        ull acc[2][4] = {};
        #pragma unroll 2
        for (int i = 0; i < 64; ++i) {
            ull bp[6];
            #pragma unroll
            for (int k = 0; k < 6; ++k) {
                float a = tile[k*1792 + i*28 + vv];
                bp[k] = pk(a, a);
            }
            #pragma unroll
            for (int opl = 0; opl < 2; ++opl) {
                const ull* w = sWtP + (i*3)*32 + og*2 + opl;
                ull w0 = w[0], w1 = w[32], w2 = w[64];
                #pragma unroll
                for (int tt = 0; tt < 4; ++tt) {
                    acc[opl][tt] = fma2(w0, bp[tt],   acc[opl][tt]);
                    acc[opl][tt] = fma2(w1, bp[tt+1], acc[opl][tt]);
                    acc[opl][tt] = fma2(w2, bp[tt+2], acc[opl][tt]);
                }
            }
        }
        #pragma unroll
        for (int opl = 0; opl < 2; ++opl) {
            int o0 = og*4 + opl*2;
            float sc0 = sscale[o0],   sh0 = sshift[o0];
            float sc1 = sscale[o0+1], sh1 = sshift[o0+1];
            size_t ob0 = ((size_t)n*64 + o0)*400;
            size_t ob1 = ((size_t)n*64 + o0+1)*400;
            #pragma unroll
            for (int tt = 0; tt < 4; ++tt) {
                float f0, f1; upk(acc[opl][tt], f0, f1);
                float y0 = tile[(tt+1)*1792 + o0*28 + vv];
                float y1 = tile[(tt+1)*1792 + (o0+1)*28 + vv];
                float v0 = y0 + f0*sc0 + sh0; v0 = fmaxf(v0, LEAKK*v0);
                float v1 = y1 + f1*sc1 + sh1; v1 = fmaxf(v1, LEAKK*v1);
                out[(ob0 + t0 + tt)*27 + vv] = v0;
                out[(ob1 + t0 + tt)*27 + vv] = v1;
            }
        }
    }
}

// ---------------------------------------------------------------------------
extern "C" void kernel_launch(void* const* d_in, const int* in_sizes, int n_in,
                              void* d_out, int out_size) {
    const float* x      = (const float*)d_in[0];
    const float* pe     = (const float*)d_in[1];
    const float* W_in   = (const float*)d_in[2];
    const float* b_in   = (const float*)d_in[3];
    const float* alphas = (const float*)d_in[4];
    const float* att0   = (const float*)d_in[5];
    const float* W_out  = (const float*)d_in[6];
    const float* b_out  = (const float*)d_in[7];
    const float* g_out  = (const float*)d_in[8];
    const float* be_out = (const float*)d_in[9];
    const float* m_out  = (const float*)d_in[10];
    const float* v_out  = (const float*)d_in[11];
    const float* W_ff   = (const float*)d_in[12];
    const float* b_ff   = (const float*)d_in[13];
    const float* g_ff   = (const float*)d_in[14];
    const float* be_ff  = (const float*)d_in[15];
    const float* m_ff   = (const float*)d_in[16];
    const float* v_ff   = (const float*)d_in[17];
    const float* W_t    = (const float*)d_in[18];
    const float* b_t    = (const float*)d_in[19];
    const float* g_t    = (const float*)d_in[20];
    const float* be_t   = (const float*)d_in[21];
    const float* m_t    = (const float*)d_in[22];
    const float* v_t    = (const float*)d_in[23];
    float* out = (float*)d_out;

    const int smemA = 7680*8 + 64*4;                               // 61,696 B
    const int smemC = 7936*8 + (7168 + 1458 + 256)*4;              //  99,016 B
    const int smemD = 6144*8 + (6*1792 + 128)*4;                   //  92,672 B
    cudaFuncSetAttribute(k_att_part, cudaFuncAttributeMaxDynamicSharedMemorySize, smemA);
    cudaFuncSetAttribute(k_main,     cudaFuncAttributeMaxDynamicSharedMemorySize, smemC);
    cudaFuncSetAttribute(k_temporal, cudaFuncAttributeMaxDynamicSharedMemorySize, smemD);

    k_att_part<<<dim3(TCH, NN), 512, smemA>>>(x, pe, W_in, b_in);
    k_att_final<<<(NN*SS*729 + 255)/256, 256>>>(alphas, att0);
    k_main<<<dim3(TT/2, NN), 512, smemC>>>(x, W_out, b_out, g_out, be_out, m_out, v_out,
                                           W_ff, b_ff, g_ff, be_ff, m_ff, v_ff);
    k_temporal<<<dim3(TT/4, NN), 512, smemD>>>(W_t, b_t, g_t, be_t, m_t, v_t, out);
}